// round 2
// baseline (speedup 1.0000x reference)
#include <cuda_runtime.h>
#include <math.h>

#define NB 32
#define CI 8
#define CO 8
#define KR 4
#define DI 16
#define DOUT 16
#define SS 32
#define NPIX 1024   // 32*32
#define PLANE (DOUT*NPIX)   // 16384

// ---------------- scratch (static device globals; no allocation) -------------
__device__ float g_pooled[NB*CO*2*PLANE];   // [b][o][2][d][u][v]  33.5 MB
__device__ float g_preroute[NB*CO*PLANE];   // [b][o][d][u][v]     16.8 MB
__device__ float g_gate[NB*CO*PLANE];       // [b][o][d][u][v]     16.8 MB
__device__ double g_part[2*CO*NB];          // BN partial sums
__device__ float g_bnab[2*CO];              // per-o BN affine (scale, offset)

// packed fp32x2 FMA (sm_103a): d = a*b + d, elementwise on float2
__device__ __forceinline__ void ffma2(float2& d, const float2 a, const float2 b) {
    asm("{.reg .b64 Ra,Rb,Rd;\n\t"
        "mov.b64 Ra,{%2,%3};\n\t"
        "mov.b64 Rb,{%4,%5};\n\t"
        "mov.b64 Rd,{%0,%1};\n\t"
        "fma.rn.f32x2 Rd, Ra, Rb, Rd;\n\t"
        "mov.b64 {%0,%1}, Rd;}"
        : "+f"(d.x), "+f"(d.y)
        : "f"(a.x), "f"(a.y), "f"(b.x), "f"(b.y));
}

// ---------------------------------------------------------------------------
// K1: fused conv_trans + value einsum + pooled(max/mean over m) + routing-pre
// grid (o=8, b=32), 512 threads, 182 KB dynamic smem
// ---------------------------------------------------------------------------
extern "C" __global__ void __launch_bounds__(512, 1)
k1_conv_route(const float* __restrict__ caps, const float* __restrict__ Wt,
              const float* __restrict__ bt, const float* __restrict__ Wv,
              const float* __restrict__ bv)
{
    extern __shared__ float sm[];
    float* s_caps  = sm;                    // 16*34*34 = 18496 (zero-padded input)
    float* s_w     = s_caps + DI*34*34;     // 8*16*144 = 18432 ([c][d][cin][3][3])
    float* s_votes = s_w + 8*16*144;        // 8*1024   = 8192
    float2* s_wp   = (float2*)(s_votes + 8*NPIX); // 128 float2 = 256 floats
    float2* s_bvp  = s_wp + 128;            // 16 float2 = 32 floats
    float* s_bias  = (float*)(s_bvp + 16);  // 128

    const int o = blockIdx.x, b = blockIdx.y;
    const int tid = threadIdx.x;

    // load padded input image for this batch
    for (int idx = tid; idx < DI*1156; idx += 512) {
        int ch = idx / 1156, rem = idx % 1156;
        int r = rem / 34, cc = rem % 34;
        float v = 0.f;
        if (r >= 1 && r <= SS && cc >= 1 && cc <= SS)
            v = caps[((b*DI + ch)*SS + (r-1))*SS + (cc-1)];
        s_caps[idx] = v;
    }
    // weights for this o: out-channel (c*8+o)*16+d
    for (int idx = tid; idx < 8*16*144; idx += 512) {
        int cd = idx / 144, j = idx % 144;
        int c = cd >> 4, d = cd & 15;
        s_w[idx] = Wt[(((c*CO + o)*DOUT + d)*144) + j];
    }
    for (int idx = tid; idx < 128; idx += 512) {
        int c = idx >> 4, d = idx & 15;
        s_bias[idx] = bt[(c*CO + o)*DOUT + d];
    }
    // packed value-conv weights: s_wp[(c2*8+ci)*2+h] = (Wv[m=2h*8+c2][ci], Wv[m=(2h+1)*8+c2][ci])
    for (int idx = tid; idx < 128; idx += 512) {
        int c2 = idx >> 4, ci = (idx >> 1) & 7, h = idx & 1;
        float wa = Wv[o*256 + ((2*h)*8 + c2)*8 + ci];
        float wb = Wv[o*256 + ((2*h+1)*8 + c2)*8 + ci];
        s_wp[idx] = make_float2(wa, wb);
    }
    if (tid < 16) {
        int c2 = tid >> 1, h = tid & 1;
        s_bvp[tid] = make_float2(bv[o*32 + (2*h)*8 + c2], bv[o*32 + (2*h+1)*8 + c2]);
    }
    __syncthreads();

    const int c  = tid >> 6;        // 0..7 (C_in channel of votes)
    const int t  = tid & 63;
    const int r  = t >> 1;          // output row 0..31
    const int cb = (t & 1) << 4;    // column base 0 or 16
    const int obase = b*CO + o;

    for (int d = 0; d < DOUT; d++) {
        // ---- Phase A: votes[c][*][*] for this d (3x3 conv over 16 ch), f32x2 pairs
        float bias = s_bias[c*16 + d];
        float2 acc2[8];
        #pragma unroll
        for (int jj = 0; jj < 8; jj++) acc2[jj] = make_float2(bias, bias);
        const float* wbase = s_w + (c*16 + d)*144;
        #pragma unroll 1
        for (int cin = 0; cin < DI; cin++) {
            const float* wc = wbase + cin*9;
            #pragma unroll
            for (int dy = 0; dy < 3; dy++) {
                const float2* xr = reinterpret_cast<const float2*>(
                    s_caps + cin*1156 + (r+dy)*34 + cb);
                float2 e[9];
                #pragma unroll
                for (int i = 0; i < 9; i++) e[i] = xr[i];
                float w0 = wc[dy*3+0], w1 = wc[dy*3+1], w2 = wc[dy*3+2];
                float2 w0p = make_float2(w0, w0);
                float2 w1p = make_float2(w1, w1);
                float2 w2p = make_float2(w2, w2);
                #pragma unroll
                for (int jj = 0; jj < 8; jj++) {
                    ffma2(acc2[jj], e[jj], w0p);
                    ffma2(acc2[jj], make_float2(e[jj].y, e[jj+1].x), w1p);
                    ffma2(acc2[jj], e[jj+1], w2p);
                }
            }
        }
        {
            float2* vr = reinterpret_cast<float2*>(s_votes + c*NPIX + r*32 + cb);
            #pragma unroll
            for (int jj = 0; jj < 8; jj++) vr[jj] = acc2[jj];
        }
        __syncthreads();

        // ---- Phase B: per-pixel 32x8 matvec (f32x2 over k-pairs) + pool + routing
        #pragma unroll
        for (int pp = 0; pp < 2; pp++) {
            int p = tid + pp*512;
            float2 vd[8];
            #pragma unroll
            for (int ci = 0; ci < 8; ci++) {
                float v = s_votes[ci*NPIX + p];
                vd[ci] = make_float2(v, v);
            }
            float vmax = -3.0e38f, vsum = 0.f;
            float meanc[8], rc[8], rmax = 0.f;
            #pragma unroll
            for (int c2 = 0; c2 < 8; c2++) {
                float2 a0 = s_bvp[c2*2 + 0];   // (k=0, k=1)
                float2 a1 = s_bvp[c2*2 + 1];   // (k=2, k=3)
                #pragma unroll
                for (int ci = 0; ci < 8; ci++) {
                    ffma2(a0, vd[ci], s_wp[(c2*8 + ci)*2 + 0]);
                    ffma2(a1, vd[ci], s_wp[(c2*8 + ci)*2 + 1]);
                }
                float v0 = a0.x, v1 = a0.y, v2 = a1.x, v3 = a1.y;
                vmax = fmaxf(vmax, fmaxf(fmaxf(v0, v1), fmaxf(v2, v3)));
                vsum += (v0 + v1) + (v2 + v3);
                float mu = 0.25f*((v0+v1) + (v2+v3));
                float d0 = v0-mu, d1 = v1-mu, d2 = v2-mu, d3 = v3-mu;
                float var = 0.25f*((d0*d0 + d1*d1) + (d2*d2 + d3*d3));
                float rr = rsqrtf(var);           // = 1/std
                meanc[c2] = mu; rc[c2] = rr;
                rmax = fmaxf(rmax, rr);
            }
            // atts = softmax(-log std) == (1/std)/sum(1/std); scaled by 1/rmax
            float inv = 1.f/rmax;
            float num = 0.f, den = 0.f;
            #pragma unroll
            for (int c2 = 0; c2 < 8; c2++) {
                float w = rc[c2]*inv;
                num += w*meanc[c2]; den += w;
            }
            float pre = num/den;
            g_pooled[(obase*2 + 0)*PLANE + d*NPIX + p] = vmax;
            g_pooled[(obase*2 + 1)*PLANE + d*NPIX + p] = vsum*(1.f/32.f);
            g_preroute[obase*PLANE + d*NPIX + p] = pre;
        }
        __syncthreads();
    }
}

// ---------------------------------------------------------------------------
// K2: spatial gate 3x3x3 conv (2ch -> 1, pad 1) + BN partial sums (fp64)
// grid (o=8, b=32), 512 threads, 166.5 KB dynamic smem
// ---------------------------------------------------------------------------
extern "C" __global__ void __launch_bounds__(512, 1)
k2_gate(const float* __restrict__ Ws)
{
    extern __shared__ float sp[];  // [2][18][34][34] zero-padded pooled
    __shared__ float s_ws[54];
    __shared__ double s_redA[16], s_redB[16];

    const int o = blockIdx.x, b = blockIdx.y;
    const int tid = threadIdx.x;
    const int obase = b*CO + o;

    if (tid < 54) s_ws[tid] = Ws[tid];
    for (int idx = tid; idx < 2*18*1156; idx += 512) {
        int ch = idx / 20808, rem = idx % 20808;
        int dd = rem / 1156, r2 = (rem % 1156)/34, cc = rem % 34;
        float v = 0.f;
        if (dd >= 1 && dd <= 16 && r2 >= 1 && r2 <= 32 && cc >= 1 && cc <= 32)
            v = g_pooled[(obase*2 + ch)*PLANE + (dd-1)*NPIX + (r2-1)*32 + (cc-1)];
        sp[idx] = v;
    }
    __syncthreads();

    const int d = tid >> 5, u = tid & 31;   // one output row per thread
    float2 acc2[16];
    #pragma unroll
    for (int jj = 0; jj < 16; jj++) acc2[jj] = make_float2(0.f, 0.f);
    #pragma unroll 1
    for (int ch = 0; ch < 2; ch++) {
        #pragma unroll 1
        for (int kd = 0; kd < 3; kd++) {
            #pragma unroll
            for (int kh = 0; kh < 3; kh++) {
                const float2* xr = reinterpret_cast<const float2*>(
                    sp + ch*20808 + (d+kd)*1156 + (u+kh)*34);
                float2 e[17];
                #pragma unroll
                for (int i = 0; i < 17; i++) e[i] = xr[i];
                const float* wp = s_ws + ch*27 + kd*9 + kh*3;
                float2 w0p = make_float2(wp[0], wp[0]);
                float2 w1p = make_float2(wp[1], wp[1]);
                float2 w2p = make_float2(wp[2], wp[2]);
                #pragma unroll
                for (int jj = 0; jj < 16; jj++) {
                    ffma2(acc2[jj], e[jj], w0p);
                    ffma2(acc2[jj], make_float2(e[jj].y, e[jj+1].x), w1p);
                    ffma2(acc2[jj], e[jj+1], w2p);
                }
            }
        }
    }
    double s = 0.0, s2 = 0.0;
    float2* gout = reinterpret_cast<float2*>(g_gate + obase*PLANE + tid*32);
    #pragma unroll
    for (int jj = 0; jj < 16; jj++) {
        gout[jj] = acc2[jj];
        double a0 = (double)acc2[jj].x, a1 = (double)acc2[jj].y;
        s += a0 + a1; s2 += a0*a0 + a1*a1;
    }
    // block-reduce the two doubles
    #pragma unroll
    for (int off = 16; off > 0; off >>= 1) {
        s  += __shfl_down_sync(0xffffffffu, s,  off);
        s2 += __shfl_down_sync(0xffffffffu, s2, off);
    }
    int w = tid >> 5;
    if ((tid & 31) == 0) { s_redA[w] = s; s_redB[w] = s2; }
    __syncthreads();
    if (tid < 32) {
        double a = (tid < 16) ? s_redA[tid] : 0.0;
        double bq = (tid < 16) ? s_redB[tid] : 0.0;
        #pragma unroll
        for (int off = 8; off > 0; off >>= 1) {
            a  += __shfl_down_sync(0xffffffffu, a,  off);
            bq += __shfl_down_sync(0xffffffffu, bq, off);
        }
        if (tid == 0) {
            g_part[o*NB + b] = a;
            g_part[CO*NB + o*NB + b] = bq;
        }
    }
}

// ---------------------------------------------------------------------------
// K2b: finalize BN stats into per-o affine
// ---------------------------------------------------------------------------
extern "C" __global__ void k2b_bn(const float* __restrict__ bng,
                                  const float* __restrict__ bnb)
{
    int o = threadIdx.x;
    if (o < CO) {
        double s = 0.0, s2 = 0.0;
        for (int b = 0; b < NB; b++) {
            s  += g_part[o*NB + b];
            s2 += g_part[CO*NB + o*NB + b];
        }
        double n = (double)NB * PLANE;
        double mu = s / n;
        double var = s2 / n - mu*mu;
        float rstd = (float)(1.0 / sqrt(var + 1e-5));
        float a = bng[0] * rstd;
        g_bnab[o] = a;
        g_bnab[CO + o] = bnb[0] - (float)mu * a;
    }
}

// ---------------------------------------------------------------------------
// K3: caps_next = (1+sigmoid(BN(g)))*preroute, then LayerNorm over (d,u,v),
// write out as [Cout, B, D, h, w]
// ---------------------------------------------------------------------------
extern "C" __global__ void __launch_bounds__(512)
k3_finalize(const float* __restrict__ lng, const float* __restrict__ lnb,
            float* __restrict__ out)
{
    __shared__ float s_red[16];
    const int o = blockIdx.x, b = blockIdx.y;
    const int tid = threadIdx.x;
    const int base = (b*CO + o)*PLANE;
    const float a = g_bnab[o], ofs = g_bnab[CO + o];

    float x[32];
    float s = 0.f;
    #pragma unroll
    for (int i = 0; i < 32; i++) {
        int idx = tid + i*512;
        float g = g_gate[base + idx];
        float z = g*a + ofs;
        float sg = 1.f / (1.f + expf(-z));
        float val = g_preroute[base + idx] * (1.f + sg);
        x[i] = val; s += val;
    }
    // reduce sum
    #pragma unroll
    for (int off = 16; off > 0; off >>= 1) s += __shfl_down_sync(0xffffffffu, s, off);
    int w = tid >> 5;
    if ((tid & 31) == 0) s_red[w] = s;
    __syncthreads();
    if (tid < 32) {
        float t = (tid < 16) ? s_red[tid] : 0.f;
        #pragma unroll
        for (int off = 8; off > 0; off >>= 1) t += __shfl_down_sync(0xffffffffu, t, off);
        if (tid == 0) s_red[0] = t;
    }
    __syncthreads();
    float m = s_red[0] * (1.f/16384.f);
    __syncthreads();

    float v = 0.f;
    #pragma unroll
    for (int i = 0; i < 32; i++) { float dd = x[i] - m; v += dd*dd; }
    #pragma unroll
    for (int off = 16; off > 0; off >>= 1) v += __shfl_down_sync(0xffffffffu, v, off);
    if ((tid & 31) == 0) s_red[w] = v;
    __syncthreads();
    if (tid < 32) {
        float t = (tid < 16) ? s_red[tid] : 0.f;
        #pragma unroll
        for (int off = 8; off > 0; off >>= 1) t += __shfl_down_sync(0xffffffffu, t, off);
        if (tid == 0) s_red[0] = t;
    }
    __syncthreads();
    float rstd = rsqrtf(s_red[0]*(1.f/16384.f) + 1e-5f);

    float* op = out + (o*NB + b)*PLANE;
    #pragma unroll
    for (int i = 0; i < 32; i++) {
        int idx = tid + i*512;
        op[idx] = (x[i] - m)*rstd*lng[idx] + lnb[idx];
    }
}

// ---------------------------------------------------------------------------
extern "C" void kernel_launch(void* const* d_in, const int* in_sizes, int n_in,
                              void* d_out, int out_size)
{
    const float* caps = (const float*)d_in[0];
    const float* Wt   = (const float*)d_in[1];
    const float* bt   = (const float*)d_in[2];
    const float* Wv   = (const float*)d_in[3];
    const float* bv   = (const float*)d_in[4];
    const float* Ws   = (const float*)d_in[5];
    const float* bng  = (const float*)d_in[6];
    const float* bnb  = (const float*)d_in[7];
    const float* lng  = (const float*)d_in[8];
    const float* lnb  = (const float*)d_in[9];
    float* out = (float*)d_out;

    const int smem1 = (DI*34*34 + 8*16*144 + 8*NPIX + 256 + 32 + 128) * 4; // 182144
    const int smem2 = (2*18*1156) * 4;                                      // 166464
    cudaFuncSetAttribute(k1_conv_route, cudaFuncAttributeMaxDynamicSharedMemorySize, smem1);
    cudaFuncSetAttribute(k2_gate,       cudaFuncAttributeMaxDynamicSharedMemorySize, smem2);

    dim3 grid(CO, NB);
    k1_conv_route<<<grid, 512, smem1>>>(caps, Wt, bt, Wv, bv);
    k2_gate<<<grid, 512, smem2>>>(Ws);
    k2b_bn<<<1, 32>>>(bng, bnb);
    k3_finalize<<<grid, 512>>>(lng, lnb, out);
}

// round 3
// speedup vs baseline: 1.7488x; 1.7488x over previous
#include <cuda_runtime.h>
#include <math.h>

#define NB 32
#define CI 8
#define CO 8
#define KR 4
#define DI 16
#define DOUT 16
#define SS 32
#define NPIX 1024   // 32*32
#define PLANE (DOUT*NPIX)   // 16384

typedef unsigned long long u64;

// ---------------- scratch (static device globals; no allocation) -------------
__device__ float g_pooled[NB*CO*2*PLANE];   // [b][o][2][d][u][v]  33.5 MB
__device__ float g_preroute[NB*CO*PLANE];   // [b][o][d][u][v]     16.8 MB
__device__ float g_gate[NB*CO*PLANE];       // [b][o][d][u][v]     16.8 MB
__device__ double g_part[2*CO*NB];          // BN partial sums
__device__ float g_bnab[2*CO];              // per-o BN affine (scale, offset)

// packed fp32x2 FMA on u64 carriers: d = a*b + d (no pack/unpack per op)
__device__ __forceinline__ void ffma2(u64& d, const u64 a, const u64 b) {
    asm("fma.rn.f32x2 %0, %1, %2, %0;" : "+l"(d) : "l"(a), "l"(b));
}
__device__ __forceinline__ u64 pack2(float x, float y) {
    u64 r; asm("mov.b64 %0, {%1,%2};" : "=l"(r) : "f"(x), "f"(y)); return r;
}
__device__ __forceinline__ float2 unpack2(u64 v) {
    float2 r; asm("mov.b64 {%0,%1}, %2;" : "=f"(r.x), "=f"(r.y) : "l"(v)); return r;
}

// ---------------------------------------------------------------------------
// K1: fused conv_trans (d-paired f32x2) + value einsum + pool + routing-pre
// grid (o=8, b=32), 512 threads, ~210 KB dynamic smem
// ---------------------------------------------------------------------------
extern "C" __global__ void __launch_bounds__(512, 1)
k1_conv_route(const float* __restrict__ caps, const float* __restrict__ Wt,
              const float* __restrict__ bt, const float* __restrict__ Wv,
              const float* __restrict__ bv)
{
    extern __shared__ float sm[];
    float* s_caps  = sm;                         // 16*34*34 = 18496 floats
    u64*   s_wpd   = (u64*)(s_caps + DI*34*34);  // 8*8*16*9 = 9216 u64 (d-paired conv w)
    float* s_votes = (float*)(s_wpd + 9216);     // 2*8*1024 = 16384 floats (2 d-planes)
    u64*   s_wp    = (u64*)(s_votes + 2*8*NPIX); // 128 u64 (k-paired Wv)
    u64*   s_bvp   = s_wp + 128;                 // 16 u64
    u64*   s_biasp = s_bvp + 16;                 // 64 u64 (d-paired bias)

    const int o = blockIdx.x, b = blockIdx.y;
    const int tid = threadIdx.x;

    // padded input image for this batch
    for (int idx = tid; idx < DI*1156; idx += 512) {
        int ch = idx / 1156, rem = idx % 1156;
        int r = rem / 34, cc = rem % 34;
        float v = 0.f;
        if (r >= 1 && r <= SS && cc >= 1 && cc <= SS)
            v = caps[((b*DI + ch)*SS + (r-1))*SS + (cc-1)];
        s_caps[idx] = v;
    }
    // conv weights pre-packed over d-pairs: s_wpd[((c*8+dp)*16+cin)*9+tap] = (w[2dp], w[2dp+1])
    for (int idx = tid; idx < 9216; idx += 512) {
        int tap = idx % 9, cin = (idx/9) & 15, dp = (idx/144) & 7, c = idx/1152;
        const float* wb = Wt + ((c*CO + o)*DOUT)*144 + cin*9 + tap;
        s_wpd[idx] = pack2(wb[(2*dp)*144], wb[(2*dp+1)*144]);
    }
    if (tid < 64) {
        int c = tid >> 3, dp = tid & 7;
        s_biasp[tid] = pack2(bt[(c*CO + o)*DOUT + 2*dp], bt[(c*CO + o)*DOUT + 2*dp+1]);
    }
    // value-conv weights k-paired: s_wp[(c2*8+ci)*2+h] = (Wv[m=2h*8+c2][ci], Wv[m=(2h+1)*8+c2][ci])
    for (int idx = tid; idx < 128; idx += 512) {
        int c2 = idx >> 4, ci = (idx >> 1) & 7, h = idx & 1;
        s_wp[idx] = pack2(Wv[o*256 + ((2*h)*8 + c2)*8 + ci],
                          Wv[o*256 + ((2*h+1)*8 + c2)*8 + ci]);
    }
    if (tid < 16) {
        int c2 = tid >> 1, h = tid & 1;
        s_bvp[tid] = pack2(bv[o*32 + (2*h)*8 + c2], bv[o*32 + (2*h+1)*8 + c2]);
    }
    __syncthreads();

    const int c  = tid >> 6;        // 0..7 (C_in channel of votes)
    const int t  = tid & 63;
    const int r  = t >> 1;          // output row 0..31
    const int cb = (t & 1) << 4;    // column base 0 or 16
    const int obase = b*CO + o;

    for (int dp = 0; dp < 8; dp++) {
        // ---- Phase A: votes for d-pair (2dp, 2dp+1): same x, paired weights
        u64 acc[16];
        {
            u64 bp = s_biasp[c*8 + dp];
            #pragma unroll
            for (int j = 0; j < 16; j++) acc[j] = bp;
        }
        const u64* wbase = s_wpd + (c*8 + dp)*144;
        #pragma unroll 1
        for (int cin = 0; cin < DI; cin++) {
            const u64* wc = wbase + cin*9;
            #pragma unroll
            for (int dy = 0; dy < 3; dy++) {
                const float2* xr = reinterpret_cast<const float2*>(
                    s_caps + cin*1156 + (r+dy)*34 + cb);
                float2 e[9];
                #pragma unroll
                for (int i = 0; i < 9; i++) e[i] = xr[i];
                u64 w0 = wc[dy*3+0], w1 = wc[dy*3+1], w2 = wc[dy*3+2];
                u64 x0 = pack2(e[0].x, e[0].x);
                u64 x1 = pack2(e[0].y, e[0].y);
                #pragma unroll
                for (int j = 0; j < 16; j++) {
                    float xn = ((j & 1) == 0) ? e[(j+2) >> 1].x : e[(j+2) >> 1].y;
                    u64 x2 = pack2(xn, xn);
                    ffma2(acc[j], x0, w0);
                    ffma2(acc[j], x1, w1);
                    ffma2(acc[j], x2, w2);
                    x0 = x1; x1 = x2;
                }
            }
        }
        {
            float* v0 = s_votes + c*NPIX + r*32 + cb;
            #pragma unroll
            for (int j = 0; j < 16; j++) {
                float2 v = unpack2(acc[j]);
                v0[j] = v.x;
                v0[8192 + j] = v.y;
            }
        }
        __syncthreads();

        // ---- Phase B: per-pixel 32x8 matvec (f32x2 over k-pairs) + pool + routing
        #pragma unroll 1
        for (int pl = 0; pl < 2; pl++) {
            int d = dp*2 + pl;
            #pragma unroll
            for (int pp = 0; pp < 2; pp++) {
                int p = tid + pp*512;
                u64 vd[8];
                #pragma unroll
                for (int ci = 0; ci < 8; ci++) {
                    float v = s_votes[pl*8192 + ci*NPIX + p];
                    vd[ci] = pack2(v, v);
                }
                float vmax = -3.0e38f, vsum = 0.f;
                float meanc[8], rc[8], rmax = 0.f;
                #pragma unroll
                for (int c2 = 0; c2 < 8; c2++) {
                    u64 a0 = s_bvp[c2*2 + 0];   // (k=0, k=1)
                    u64 a1 = s_bvp[c2*2 + 1];   // (k=2, k=3)
                    #pragma unroll
                    for (int ci = 0; ci < 8; ci++) {
                        ffma2(a0, vd[ci], s_wp[(c2*8 + ci)*2 + 0]);
                        ffma2(a1, vd[ci], s_wp[(c2*8 + ci)*2 + 1]);
                    }
                    float2 p0 = unpack2(a0), p1 = unpack2(a1);
                    float v0 = p0.x, v1 = p0.y, v2 = p1.x, v3 = p1.y;
                    vmax = fmaxf(vmax, fmaxf(fmaxf(v0, v1), fmaxf(v2, v3)));
                    vsum += (v0 + v1) + (v2 + v3);
                    float mu = 0.25f*((v0+v1) + (v2+v3));
                    float d0 = v0-mu, d1 = v1-mu, d2 = v2-mu, d3 = v3-mu;
                    float var = 0.25f*((d0*d0 + d1*d1) + (d2*d2 + d3*d3));
                    float rr = rsqrtf(var);           // = 1/std
                    meanc[c2] = mu; rc[c2] = rr;
                    rmax = fmaxf(rmax, rr);
                }
                // atts = softmax(-log std) == (1/std)/sum(1/std); scaled by 1/rmax
                float inv = 1.f/rmax;
                float num = 0.f, den = 0.f;
                #pragma unroll
                for (int c2 = 0; c2 < 8; c2++) {
                    float w = rc[c2]*inv;
                    num += w*meanc[c2]; den += w;
                }
                float pre = num/den;
                g_pooled[(obase*2 + 0)*PLANE + d*NPIX + p] = vmax;
                g_pooled[(obase*2 + 1)*PLANE + d*NPIX + p] = vsum*(1.f/32.f);
                g_preroute[obase*PLANE + d*NPIX + p] = pre;
            }
        }
        __syncthreads();
    }
}

// ---------------------------------------------------------------------------
// K2: spatial gate 3x3x3 conv (2ch -> 1, pad 1) + BN partial sums (fp64)
// grid (o=8, b=32), 512 threads, 166.5 KB dynamic smem  [R1 scalar form]
// ---------------------------------------------------------------------------
extern "C" __global__ void __launch_bounds__(512, 1)
k2_gate(const float* __restrict__ Ws)
{
    extern __shared__ float sp[];  // [2][18][34][34] zero-padded pooled
    __shared__ float s_ws[54];
    __shared__ double s_redA[16], s_redB[16];

    const int o = blockIdx.x, b = blockIdx.y;
    const int tid = threadIdx.x;
    const int obase = b*CO + o;

    if (tid < 54) s_ws[tid] = Ws[tid];
    for (int idx = tid; idx < 2*18*1156; idx += 512) {
        int ch = idx / 20808, rem = idx % 20808;
        int dd = rem / 1156, r2 = (rem % 1156)/34, cc = rem % 34;
        float v = 0.f;
        if (dd >= 1 && dd <= 16 && r2 >= 1 && r2 <= 32 && cc >= 1 && cc <= 32)
            v = g_pooled[(obase*2 + ch)*PLANE + (dd-1)*NPIX + (r2-1)*32 + (cc-1)];
        sp[idx] = v;
    }
    __syncthreads();

    const int d = tid >> 5, u = tid & 31;   // one output row per thread
    float acc[32];
    #pragma unroll
    for (int v = 0; v < 32; v++) acc[v] = 0.f;
    #pragma unroll 1
    for (int ch = 0; ch < 2; ch++) {
        #pragma unroll
        for (int kd = 0; kd < 3; kd++) {
            #pragma unroll
            for (int kh = 0; kh < 3; kh++) {
                const float* xr = sp + ch*20808 + (d+kd)*1156 + (u+kh)*34;
                float xx[34];
                #pragma unroll
                for (int j = 0; j < 34; j++) xx[j] = xr[j];
                const float* wp = s_ws + ch*27 + kd*9 + kh*3;
                float w0 = wp[0], w1 = wp[1], w2 = wp[2];
                #pragma unroll
                for (int v = 0; v < 32; v++)
                    acc[v] += w0*xx[v] + w1*xx[v+1] + w2*xx[v+2];
            }
        }
    }
    double s = 0.0, s2 = 0.0;
    float* gout = g_gate + obase*PLANE + tid*32;
    #pragma unroll
    for (int v = 0; v < 32; v++) {
        gout[v] = acc[v];
        double dv = (double)acc[v];
        s += dv; s2 += dv*dv;
    }
    #pragma unroll
    for (int off = 16; off > 0; off >>= 1) {
        s  += __shfl_down_sync(0xffffffffu, s,  off);
        s2 += __shfl_down_sync(0xffffffffu, s2, off);
    }
    int w = tid >> 5;
    if ((tid & 31) == 0) { s_redA[w] = s; s_redB[w] = s2; }
    __syncthreads();
    if (tid < 32) {
        double a = (tid < 16) ? s_redA[tid] : 0.0;
        double bq = (tid < 16) ? s_redB[tid] : 0.0;
        #pragma unroll
        for (int off = 8; off > 0; off >>= 1) {
            a  += __shfl_down_sync(0xffffffffu, a,  off);
            bq += __shfl_down_sync(0xffffffffu, bq, off);
        }
        if (tid == 0) {
            g_part[o*NB + b] = a;
            g_part[CO*NB + o*NB + b] = bq;
        }
    }
}

// ---------------------------------------------------------------------------
// K2b: finalize BN stats into per-o affine
// ---------------------------------------------------------------------------
extern "C" __global__ void k2b_bn(const float* __restrict__ bng,
                                  const float* __restrict__ bnb)
{
    int o = threadIdx.x;
    if (o < CO) {
        double s = 0.0, s2 = 0.0;
        for (int b = 0; b < NB; b++) {
            s  += g_part[o*NB + b];
            s2 += g_part[CO*NB + o*NB + b];
        }
        double n = (double)NB * PLANE;
        double mu = s / n;
        double var = s2 / n - mu*mu;
        float rstd = (float)(1.0 / sqrt(var + 1e-5));
        float a = bng[0] * rstd;
        g_bnab[o] = a;
        g_bnab[CO + o] = bnb[0] - (float)mu * a;
    }
}

// ---------------------------------------------------------------------------
// K3: caps_next = (1+sigmoid(BN(g)))*preroute, then LayerNorm over (d,u,v),
// write out as [Cout, B, D, h, w]
// ---------------------------------------------------------------------------
extern "C" __global__ void __launch_bounds__(512)
k3_finalize(const float* __restrict__ lng, const float* __restrict__ lnb,
            float* __restrict__ out)
{
    __shared__ float s_red[16];
    const int o = blockIdx.x, b = blockIdx.y;
    const int tid = threadIdx.x;
    const int base = (b*CO + o)*PLANE;
    const float a = g_bnab[o], ofs = g_bnab[CO + o];

    float x[32];
    float s = 0.f;
    #pragma unroll
    for (int i = 0; i < 32; i++) {
        int idx = tid + i*512;
        float g = g_gate[base + idx];
        float z = g*a + ofs;
        float sg = 1.f / (1.f + expf(-z));
        float val = g_preroute[base + idx] * (1.f + sg);
        x[i] = val; s += val;
    }
    #pragma unroll
    for (int off = 16; off > 0; off >>= 1) s += __shfl_down_sync(0xffffffffu, s, off);
    int w = tid >> 5;
    if ((tid & 31) == 0) s_red[w] = s;
    __syncthreads();
    if (tid < 32) {
        float t = (tid < 16) ? s_red[tid] : 0.f;
        #pragma unroll
        for (int off = 8; off > 0; off >>= 1) t += __shfl_down_sync(0xffffffffu, t, off);
        if (tid == 0) s_red[0] = t;
    }
    __syncthreads();
    float m = s_red[0] * (1.f/16384.f);
    __syncthreads();

    float v = 0.f;
    #pragma unroll
    for (int i = 0; i < 32; i++) { float dd = x[i] - m; v += dd*dd; }
    #pragma unroll
    for (int off = 16; off > 0; off >>= 1) v += __shfl_down_sync(0xffffffffu, v, off);
    if ((tid & 31) == 0) s_red[w] = v;
    __syncthreads();
    if (tid < 32) {
        float t = (tid < 16) ? s_red[tid] : 0.f;
        #pragma unroll
        for (int off = 8; off > 0; off >>= 1) t += __shfl_down_sync(0xffffffffu, t, off);
        if (tid == 0) s_red[0] = t;
    }
    __syncthreads();
    float rstd = rsqrtf(s_red[0]*(1.f/16384.f) + 1e-5f);

    float* op = out + (o*NB + b)*PLANE;
    #pragma unroll
    for (int i = 0; i < 32; i++) {
        int idx = tid + i*512;
        op[idx] = (x[i] - m)*rstd*lng[idx] + lnb[idx];
    }
}

// ---------------------------------------------------------------------------
extern "C" void kernel_launch(void* const* d_in, const int* in_sizes, int n_in,
                              void* d_out, int out_size)
{
    const float* caps = (const float*)d_in[0];
    const float* Wt   = (const float*)d_in[1];
    const float* bt   = (const float*)d_in[2];
    const float* Wv   = (const float*)d_in[3];
    const float* bv   = (const float*)d_in[4];
    const float* Ws   = (const float*)d_in[5];
    const float* bng  = (const float*)d_in[6];
    const float* bnb  = (const float*)d_in[7];
    const float* lng  = (const float*)d_in[8];
    const float* lnb  = (const float*)d_in[9];
    float* out = (float*)d_out;

    // 18496 + 18432(u64 wpd) + 16384 + 256 + 32 + 128 floats = 53728 f = 214912 B
    const int smem1 = (DI*34*34 + 9216*2 + 2*8*NPIX + 256 + 32 + 128) * 4;
    const int smem2 = (2*18*1156) * 4;                                      // 166464
    cudaFuncSetAttribute(k1_conv_route, cudaFuncAttributeMaxDynamicSharedMemorySize, smem1);
    cudaFuncSetAttribute(k2_gate,       cudaFuncAttributeMaxDynamicSharedMemorySize, smem2);

    dim3 grid(CO, NB);
    k1_conv_route<<<grid, 512, smem1>>>(caps, Wt, bt, Wv, bv);
    k2_gate<<<grid, 512, smem2>>>(Ws);
    k2b_bn<<<1, 32>>>(bng, bnb);
    k3_finalize<<<grid, 512>>>(lng, lnb, out);
}